// round 17
// baseline (speedup 1.0000x reference)
#include <cuda_runtime.h>

#define BB 8
#define FF 1024
#define KK 4096
#define NN 9216

// ---- 8-CTA cluster config (verified fallback) ----
#define CTAS8 8
#define PPC8 1152     // NN / 8
#define BPC8 512      // KK / 8
// ---- 16-CTA cluster config (preferred) ----
#define CTAS16 16
#define PPC16 576     // NN / 16
#define BPC16 256     // KK / 16

// Scratch (device globals; zero at module load; every call restores invariants)
__device__ int  g_hist[BB * KK];     // per-batch voxel histogram (zero on entry)
__device__ int  g_off[BB * KK];      // scatter cursor per voxel
__device__ int2 g_slotSC[BB * KK];   // per output slot (rank): {start, count}
__device__ int  g_sorted[BB * NN];   // point indices grouped by voxel
__device__ int  g_count[BB];         // occupied voxels per batch
__device__ int  g_ctot[BB * CTAS16]; // per-CTA scan totals (overwritten each call)

#define CLUSTER_SYNC() do { \
    asm volatile("barrier.cluster.arrive.aligned;" ::: "memory"); \
    asm volatile("barrier.cluster.wait.aligned;" ::: "memory"); \
} while (0)

// Compact voxel id: cx*256+cy*16+cz preserves the reference HASH_M=1024
// lexicographic ordering; the per-batch min subtraction is a constant per-axis
// shift and changes neither grouping nor order, hence ranks are unchanged.
__device__ __forceinline__ int voxel_id(const float* __restrict__ bx, int i) {
    float x = bx[i * 3 + 0];
    float y = bx[i * 3 + 1];
    float z = bx[i * 3 + 2];
    int cx = (int)floorf(__fdiv_rn(x, 0.2f));
    int cy = (int)floorf(__fdiv_rn(y, 0.2f));
    int cz = (int)floorf(__fdiv_rn(z, 0.2f));
    cx = min(max(cx, 0), 15);
    cy = min(max(cy, 0), 15);
    cz = min(max(cz, 0), 15);
    return (cx << 8) | (cy << 4) | cz;
}

// ============================================================================
// Build, 16-CTA cluster per batch (preferred): grid (16, BB) x 256.
// Per CTA: 576 points (threads 0..63 own 3, rest own 2), 256 bins (1/thread).
// 8 clusters of 16 CTAs map onto the 8 GPCs.
// ============================================================================
__global__ __launch_bounds__(256) __cluster_dims__(CTAS16, 1, 1)
void build_kernel16(const float* __restrict__ xyz) {
    const int b = blockIdx.y;
    const int r = blockIdx.x;
    const int t = threadIdx.x;
    const int lane = t & 31;
    const int wid = t >> 5;

    __shared__ int wsum[8];
    __shared__ int s_base;

    // zero this CTA's slice of the slot table (empty ranks => zero rows)
    g_slotSC[b * KK + r * BPC16 + t] = make_int2(0, 0);

    // ---- Phase 1: voxelize own points (ids in regs) + histogram ----
    const float* bx = xyz + (size_t)b * NN * 3;
    int vid[3], pid[3];
    int np = (t < PPC16 - 2 * 256) ? 3 : 2;   // first 64 threads own 3 points
#pragma unroll
    for (int k = 0; k < 3; k++) {
        if (k < np) {
            int i = r * PPC16 + t + k * 256;
            pid[k] = i;
            vid[k] = voxel_id(bx, i);
            atomicAdd(&g_hist[b * KK + vid[k]], 1);
        }
    }

    CLUSTER_SYNC();

    // ---- Phase 2: packed dual exclusive scan (1 bin/thread, 256 bins/CTA) ----
    const int bin = b * KK + r * BPC16 + t;
    int c = g_hist[bin];
    int e = c | ((c > 0) << 16);

    int incl = e;
#pragma unroll
    for (int off = 1; off < 32; off <<= 1) {
        int n = __shfl_up_sync(0xffffffffu, incl, off);
        if (lane >= off) incl += n;
    }
    if (lane == 31) wsum[wid] = incl;
    __syncthreads();

    if (wid == 0 && lane < 8) {
        int wv = wsum[lane];
        int wi = wv;
#pragma unroll
        for (int off = 1; off < 8; off <<= 1) {
            int n = __shfl_up_sync(0xffu, wi, off);
            if (lane >= off) wi += n;
        }
        wsum[lane] = wi - wv;
        if (lane == 7) g_ctot[b * CTAS16 + r] = wi;   // CTA total
    }
    __syncthreads();
    const int localExcl = wsum[wid] + (incl - e);

    CLUSTER_SYNC();

    if (t == 0) {
        int base = 0;
#pragma unroll
        for (int j = 0; j < CTAS16; j++) {
            int v = g_ctot[b * CTAS16 + j];
            if (j < r) base += v;
            if (r == CTAS16 - 1 && j == CTAS16 - 1) g_count[b] = ((base + v) >> 16);
        }
        s_base = base;
    }
    __syncthreads();

    int pref = s_base + localExcl;
    int start = pref & 0xFFFF;
    int rank = pref >> 16;
    if (c > 0) g_slotSC[b * KK + rank] = make_int2(start, c);
    g_off[bin] = start;
    g_hist[bin] = 0;

    CLUSTER_SYNC();

    // ---- Phase 3: counting-sort scatter from register-held ids ----
#pragma unroll
    for (int k = 0; k < 3; k++) {
        if (k < np) {
            int pos = atomicAdd(&g_off[b * KK + vid[k]], 1);
            g_sorted[b * NN + pos] = pid[k];
        }
    }
}

// ============================================================================
// Build, 8-CTA cluster per batch (verified fallback): grid (8, BB) x 512.
// ============================================================================
__global__ __launch_bounds__(512) __cluster_dims__(CTAS8, 1, 1)
void build_kernel8(const float* __restrict__ xyz) {
    const int b = blockIdx.y;
    const int r = blockIdx.x;
    const int t = threadIdx.x;
    const int lane = t & 31;
    const int wid = t >> 5;

    __shared__ int wsum[16];
    __shared__ int s_base;

    g_slotSC[b * KK + r * BPC8 + t] = make_int2(0, 0);

    const float* bx = xyz + (size_t)b * NN * 3;
    int vid[3], pid[3];
    int np = (t < PPC8 - 2 * BPC8) ? 3 : 2;
#pragma unroll
    for (int k = 0; k < 3; k++) {
        if (k < np) {
            int i = r * PPC8 + t + k * BPC8;
            pid[k] = i;
            vid[k] = voxel_id(bx, i);
            atomicAdd(&g_hist[b * KK + vid[k]], 1);
        }
    }

    CLUSTER_SYNC();

    const int bin = b * KK + r * BPC8 + t;
    int c = g_hist[bin];
    int e = c | ((c > 0) << 16);

    int incl = e;
#pragma unroll
    for (int off = 1; off < 32; off <<= 1) {
        int n = __shfl_up_sync(0xffffffffu, incl, off);
        if (lane >= off) incl += n;
    }
    if (lane == 31) wsum[wid] = incl;
    __syncthreads();

    if (wid == 0 && lane < 16) {
        int wv = wsum[lane];
        int wi = wv;
#pragma unroll
        for (int off = 1; off < 16; off <<= 1) {
            int n = __shfl_up_sync(0xffffu, wi, off);
            if (lane >= off) wi += n;
        }
        wsum[lane] = wi - wv;
        if (lane == 15) g_ctot[b * CTAS16 + r] = wi;  // reuse ctot array
    }
    __syncthreads();
    const int localExcl = wsum[wid] + (incl - e);

    CLUSTER_SYNC();

    if (t == 0) {
        int base = 0;
#pragma unroll
        for (int j = 0; j < CTAS8; j++) {
            int v = g_ctot[b * CTAS16 + j];
            if (j < r) base += v;
            if (r == CTAS8 - 1 && j == CTAS8 - 1) g_count[b] = ((base + v) >> 16);
        }
        s_base = base;
    }
    __syncthreads();

    int pref = s_base + localExcl;
    int start = pref & 0xFFFF;
    int rank = pref >> 16;
    if (c > 0) g_slotSC[b * KK + rank] = make_int2(start, c);
    g_off[bin] = start;
    g_hist[bin] = 0;

    CLUSTER_SYNC();

#pragma unroll
    for (int k = 0; k < 3; k++) {
        if (k < np) {
            int pos = atomicAdd(&g_off[b * KK + vid[k]], 1);
            g_sorted[b * NN + pos] = pid[k];
        }
    }
}

// ============================================================================
// Pool — R16 verbatim (66.0us, DRAM 76.7%, regs 32, occ 88%): one block per
// TWO output rows; fixed-width 4-load clamped batches (unconditional LDG.128s,
// >=512B in flight/warp; duplicates hit L1/L2 — zero extra DRAM traffic);
// both slots' index words prefetched before the slot loop; v[4] reused across
// slots so regs stay 32. Block (0,0) writes the batch_offset tail.
// ============================================================================
__global__ __launch_bounds__(256) void pool_kernel(const float* __restrict__ feat,
                                                   float* __restrict__ out,
                                                   float* __restrict__ out_tail) {
    const int b = blockIdx.y;
    const int t = threadIdx.x;
    const int lane = t & 31;
    const float4* fb = reinterpret_cast<const float4*>(feat) + (size_t)b * NN * (FF / 4);

    if (out_tail != nullptr && blockIdx.x == 0 && b == 0 && t == 0) {
        int acc = 0;
#pragma unroll
        for (int i = 0; i < BB; i++) {
            acc += g_count[i];
            out_tail[i] = (float)acc;
        }
    }

    const int slot0 = b * KK + blockIdx.x * 2;
    const int2 sc0 = g_slotSC[slot0];
    const int2 sc1 = g_slotSC[slot0 + 1];

    const int* sp0 = g_sorted + b * NN + sc0.x;
    const int* sp1 = g_sorted + b * NN + sc1.x;

    int myidx0 = (sc0.y > 0 && lane < min(sc0.y, 32)) ? sp0[lane] : 0;
    int myidx1 = (sc1.y > 0 && lane < min(sc1.y, 32)) ? sp1[lane] : 0;

#pragma unroll
    for (int s = 0; s < 2; s++) {
        const int slot = slot0 + s;
        const int2 sc = (s == 0) ? sc0 : sc1;
        const int* sp = (s == 0) ? sp0 : sp1;
        const int myidx = (s == 0) ? myidx0 : myidx1;
        float4* o = reinterpret_cast<float4*>(out) + (size_t)slot * (FF / 4);
        const int cnt = sc.y;
        if (cnt == 0) {
            __stcs(&o[t], make_float4(0.f, 0.f, 0.f, 0.f));
            continue;
        }

        const int m32 = min(cnt, 32);
        float4 acc = make_float4(0.f, 0.f, 0.f, 0.f);

        for (int j0 = 0; j0 < m32; j0 += 4) {
            float4 v[4];
#pragma unroll
            for (int j = 0; j < 4; j++) {
                int jj = min(j0 + j, cnt - 1) & 31;
                int idx = __shfl_sync(0xffffffffu, myidx, jj);
                v[j] = __ldcs(&fb[(size_t)idx * (FF / 4) + t]);
            }
#pragma unroll
            for (int j = 0; j < 4; j++) {
                if (j0 + j < cnt) {
                    acc.x += v[j].x; acc.y += v[j].y;
                    acc.z += v[j].z; acc.w += v[j].w;
                }
            }
        }
        for (int base = 32; base < cnt; base += 32) {
            int m = min(32, cnt - base);
            int widx = (lane < m) ? sp[base + lane] : 0;
            for (int j = 0; j < m; j++) {
                int idx = __shfl_sync(0xffffffffu, widx, j);
                float4 v = __ldcs(&fb[(size_t)idx * (FF / 4) + t]);
                acc.x += v.x; acc.y += v.y; acc.z += v.z; acc.w += v.w;
            }
        }

        float inv = 1.0f / (float)cnt;
        __stcs(&o[t], make_float4(acc.x * inv, acc.y * inv, acc.z * inv, acc.w * inv));
    }
}

extern "C" void kernel_launch(void* const* d_in, const int* in_sizes, int n_in,
                              void* d_out, int out_size) {
    const float* features = (const float*)d_in[0];
    const float* xyz = (const float*)d_in[1];
    if (n_in >= 2 && in_sizes[0] < in_sizes[1]) {
        features = (const float*)d_in[1];
        xyz = (const float*)d_in[0];
    }
    float* out = (float*)d_out;
    float* tail = (out_size > BB * KK * FF) ? out + (size_t)BB * KK * FF : nullptr;

    // Prefer the 16-CTA cluster build; gate on the non-portable-cluster
    // opt-in (host-side attribute set: not a stream op, capture-safe,
    // idempotent and deterministic). Fall back to the verified 8-CTA build.
    cudaError_t rc = cudaFuncSetAttribute(
        build_kernel16, cudaFuncAttributeNonPortableClusterSizeAllowed, 1);
    if (rc == cudaSuccess) {
        dim3 g16(CTAS16, BB);
        build_kernel16<<<g16, 256>>>(xyz);
    } else {
        cudaGetLastError();  // clear the attribute error
        dim3 g8(CTAS8, BB);
        build_kernel8<<<g8, 512>>>(xyz);
    }

    dim3 gpool(KK / 2, BB);
    pool_kernel<<<gpool, 256>>>(features, out, tail);
}